// round 1
// baseline (speedup 1.0000x reference)
#include <cuda_runtime.h>

#define QLEN 1024
#define MLEN 1024
#define KLEN 2048
#define RLEN 2048
#define BSZ 4
#define NH 16
#define DH 64
#define DM 1024
#define LN_EPS 1e-5f

// ---------------- scratch (static device globals; no allocs allowed) ------
__device__ float g_Qh[QLEN * BSZ * DM];   // 16 MB
__device__ float g_Kh[KLEN * BSZ * DM];   // 32 MB
__device__ float g_Vh[KLEN * BSZ * DM];   // 32 MB
__device__ float g_Rh[RLEN * DM];         //  8 MB
__device__ float g_att[QLEN * BSZ * DM];  // 16 MB (attn_vec)
__device__ float g_ao[QLEN * BSZ * DM];   // 16 MB (attn_out)

// ---------------- SGEMM: C[M,N] = A[M,K] @ B[K,N], A rows split across two
// source tensors at 'split' (for cat = [mems; content]). 128x128 block tile,
// 256 threads, 8-wide k-step, 8x8 per thread (split 4+4 fragments). ---------
__global__ __launch_bounds__(256) void sgemm_cat(
    const float* __restrict__ A0, const float* __restrict__ A1, int split,
    const float* __restrict__ B, float* __restrict__ C, int M, int N, int K)
{
    __shared__ float As[8][129];
    __shared__ float Bs[8][128];
    const int t  = threadIdx.x;
    const int bm = blockIdx.y * 128, bn = blockIdx.x * 128;
    const int tm = (t >> 4), tn = (t & 15);
    const int a_m = t >> 1;          // 0..127
    const int a_k = (t & 1) * 4;     // 0 or 4
    const int b_k = t >> 5;          // 0..7
    const int b_n = (t & 31) * 4;    // 0..124

    const float* Arow;
    {
        int gm = bm + a_m;
        Arow = (gm < split) ? (A0 + (size_t)gm * K)
                            : (A1 + (size_t)(gm - split) * K);
    }
    const float* Bp = B + (size_t)b_k * N + bn + b_n;

    float acc[8][8];
#pragma unroll
    for (int i = 0; i < 8; i++)
#pragma unroll
        for (int j = 0; j < 8; j++) acc[i][j] = 0.f;

    for (int k0 = 0; k0 < K; k0 += 8) {
        float4 av = *(const float4*)(Arow + k0 + a_k);
        float4 bv = *(const float4*)(Bp + (size_t)k0 * N);
        __syncthreads();
        As[a_k + 0][a_m] = av.x;
        As[a_k + 1][a_m] = av.y;
        As[a_k + 2][a_m] = av.z;
        As[a_k + 3][a_m] = av.w;
        *(float4*)&Bs[b_k][b_n] = bv;
        __syncthreads();
#pragma unroll
        for (int kk = 0; kk < 8; kk++) {
            float a[8], bb[8];
#pragma unroll
            for (int i = 0; i < 4; i++) {
                a[i]     = As[kk][tm * 4 + i];
                a[4 + i] = As[kk][64 + tm * 4 + i];
            }
            float4 v0 = *(float4*)&Bs[kk][tn * 4];
            float4 v1 = *(float4*)&Bs[kk][64 + tn * 4];
            bb[0] = v0.x; bb[1] = v0.y; bb[2] = v0.z; bb[3] = v0.w;
            bb[4] = v1.x; bb[5] = v1.y; bb[6] = v1.z; bb[7] = v1.w;
#pragma unroll
            for (int i = 0; i < 8; i++)
#pragma unroll
                for (int j = 0; j < 8; j++) acc[i][j] += a[i] * bb[j];
        }
    }
#pragma unroll
    for (int i = 0; i < 8; i++) {
        int gm = bm + ((i < 4) ? (tm * 4 + i) : (64 + tm * 4 + (i - 4)));
        float* Cp = C + (size_t)gm * N + bn;
        float4 w0 = make_float4(acc[i][0], acc[i][1], acc[i][2], acc[i][3]);
        float4 w1 = make_float4(acc[i][4], acc[i][5], acc[i][6], acc[i][7]);
        *(float4*)(Cp + tn * 4)      = w0;
        *(float4*)(Cp + 64 + tn * 4) = w1;
    }
}

// ---------------- fused flash attention with TXL relative shift -----------
// score[i,j] = scale*((Q[i]+rwb)·K[j] + (Q[i]+rrb)·R[j-i+QLEN-1]), mask j>i+MLEN
// Block: 64 queries for one (b, n). 256 threads (16x16), online softmax.
// Column mapping jj = tx + 16*c keeps smem K/R reads at <=2-way conflict.
#define BI 64
#define BJ 64
#define SSTR 68

__global__ __launch_bounds__(256) void attn_kernel(
    const float* __restrict__ rwb, const float* __restrict__ rrb)
{
    extern __shared__ float sm[];
    float* sQa = sm;                 // [64][68]  Q + r_w_bias
    float* sQb = sQa + BI * SSTR;    // [64][68]  Q + r_r_bias
    float* sK  = sQb + BI * SSTR;    // [64][68]
    float* sV  = sK + BJ * SSTR;     // [64][68]
    float* sP  = sV + BJ * SSTR;     // [64][68]
    float* sR  = sP + BI * SSTR;     // [128][68]

    const int t  = threadIdx.x;
    const int tx = t & 15, ty = t >> 4;
    const int i0 = blockIdx.x * BI;
    const int b  = blockIdx.y;
    const int n  = blockIdx.z;
    const int hd = n * DH;
    const float scale = 0.125f;  // 1/sqrt(64)

    // load Q tile + both biases
    for (int e = t * 4; e < BI * DH; e += 1024) {
        int row = e >> 6, d = e & 63;
        float4 q  = *(const float4*)&g_Qh[((size_t)(i0 + row) * BSZ + b) * DM + hd + d];
        float4 wb = *(const float4*)&rwb[hd + d];
        float4 rb = *(const float4*)&rrb[hd + d];
        float* pa = &sQa[row * SSTR + d];
        pa[0] = q.x + wb.x; pa[1] = q.y + wb.y; pa[2] = q.z + wb.z; pa[3] = q.w + wb.w;
        float* pb = &sQb[row * SSTR + d];
        pb[0] = q.x + rb.x; pb[1] = q.y + rb.y; pb[2] = q.z + rb.z; pb[3] = q.w + rb.w;
    }

    float Oacc[4][4];
    float mprev[4], lsum[4];
#pragma unroll
    for (int r = 0; r < 4; r++) {
        mprev[r] = -1e30f; lsum[r] = 0.f;
#pragma unroll
        for (int c = 0; c < 4; c++) Oacc[r][c] = 0.f;
    }

    const int ntiles = blockIdx.x + 17;  // j <= i + MLEN => j0max = i0 + 1024
    for (int jt = 0; jt < ntiles; jt++) {
        const int j0 = jt * BJ;
        __syncthreads();
        // load K, V tiles
        for (int e = t * 4; e < BJ * DH; e += 1024) {
            int row = e >> 6, d = e & 63;
            size_t g = ((size_t)(j0 + row) * BSZ + b) * DM + hd + d;
            *(float4*)&sK[row * SSTR + d] = *(const float4*)&g_Kh[g];
            *(float4*)&sV[row * SSTR + d] = *(const float4*)&g_Vh[g];
        }
        // load R rows: local row tloc maps to ridx = j0-i0+(QLEN-BI)+tloc
        for (int e = t * 4; e < 2 * BI * DH; e += 1024) {
            int row = e >> 6, d = e & 63;
            int ridx = j0 - i0 + (QLEN - BI) + row;
            float4 rv = make_float4(0.f, 0.f, 0.f, 0.f);
            if (ridx >= 0 && ridx < RLEN)
                rv = *(const float4*)&g_Rh[(size_t)ridx * DM + hd + d];
            *(float4*)&sR[row * SSTR + d] = rv;
        }
        __syncthreads();

        float accS[4][4];
#pragma unroll
        for (int r = 0; r < 4; r++)
#pragma unroll
            for (int c = 0; c < 4; c++) accS[r][c] = 0.f;

        // AC = (Q + rwb) . K
#pragma unroll
        for (int d = 0; d < DH; d += 4) {
            float4 qa[4], kk[4];
#pragma unroll
            for (int r = 0; r < 4; r++) qa[r] = *(const float4*)&sQa[(ty * 4 + r) * SSTR + d];
#pragma unroll
            for (int c = 0; c < 4; c++) kk[c] = *(const float4*)&sK[(tx + 16 * c) * SSTR + d];
#pragma unroll
            for (int r = 0; r < 4; r++)
#pragma unroll
                for (int c = 0; c < 4; c++)
                    accS[r][c] += qa[r].x * kk[c].x + qa[r].y * kk[c].y +
                                  qa[r].z * kk[c].z + qa[r].w * kk[c].w;
        }
        // BD = (Q + rrb) . R[j - i + 1023]   (local row = jj - ii + 63)
        const int rb0 = tx - ty * 4 + 63;
#pragma unroll
        for (int d = 0; d < DH; d += 4) {
            float4 qb[4];
#pragma unroll
            for (int r = 0; r < 4; r++) qb[r] = *(const float4*)&sQb[(ty * 4 + r) * SSTR + d];
#pragma unroll
            for (int r = 0; r < 4; r++)
#pragma unroll
                for (int c = 0; c < 4; c++) {
                    float4 rv = *(const float4*)&sR[(rb0 + 16 * c - r) * SSTR + d];
                    accS[r][c] += qb[r].x * rv.x + qb[r].y * rv.y +
                                  qb[r].z * rv.z + qb[r].w * rv.w;
                }
        }

        // mask + scale + online softmax
#pragma unroll
        for (int r = 0; r < 4; r++) {
            int gi = i0 + ty * 4 + r;
            float mx = -1e30f;
#pragma unroll
            for (int c = 0; c < 4; c++) {
                int gj = j0 + tx + 16 * c;
                float s = (gj > gi + MLEN) ? -1e30f : accS[r][c] * scale;
                accS[r][c] = s;
                mx = fmaxf(mx, s);
            }
#pragma unroll
            for (int o = 1; o < 16; o <<= 1)
                mx = fmaxf(mx, __shfl_xor_sync(0xffffffffu, mx, o));
            float mnew = fmaxf(mprev[r], mx);
            float s4 = 0.f;
            float p[4];
#pragma unroll
            for (int c = 0; c < 4; c++) {
                p[c] = __expf(accS[r][c] - mnew);
                s4 += p[c];
            }
#pragma unroll
            for (int o = 1; o < 16; o <<= 1)
                s4 += __shfl_xor_sync(0xffffffffu, s4, o);
            float corr = __expf(mprev[r] - mnew);
            lsum[r] = lsum[r] * corr + s4;
            mprev[r] = mnew;
#pragma unroll
            for (int c = 0; c < 4; c++) {
                Oacc[r][c] *= corr;
                sP[(ty * 4 + r) * SSTR + tx + 16 * c] = p[c];
            }
        }
        __syncthreads();

        // O += P @ V   (thread owns rows ty*4+r, d-cols tx*4..tx*4+3)
#pragma unroll 16
        for (int jj = 0; jj < BJ; jj++) {
            float4 v = *(const float4*)&sV[jj * SSTR + tx * 4];
#pragma unroll
            for (int r = 0; r < 4; r++) {
                float pr = sP[(ty * 4 + r) * SSTR + jj];
                Oacc[r][0] += pr * v.x;
                Oacc[r][1] += pr * v.y;
                Oacc[r][2] += pr * v.z;
                Oacc[r][3] += pr * v.w;
            }
        }
    }

    // normalize + write attn_vec [i, b, n*64+d]
#pragma unroll
    for (int r = 0; r < 4; r++) {
        float inv = 1.f / lsum[r];
        float4 w = make_float4(Oacc[r][0] * inv, Oacc[r][1] * inv,
                               Oacc[r][2] * inv, Oacc[r][3] * inv);
        *(float4*)&g_att[((size_t)(i0 + ty * 4 + r) * BSZ + b) * DM + hd + tx * 4] = w;
    }
}

// ---------------- residual add + LayerNorm --------------------------------
__global__ __launch_bounds__(256) void add_ln_kernel(
    const float* __restrict__ q, const float* __restrict__ x,
    const float* __restrict__ gamma, const float* __restrict__ beta,
    float* __restrict__ out)
{
    const int row = blockIdx.x;
    const int t = threadIdx.x;
    __shared__ float red[8];
    __shared__ float s_mu, s_var;

    float4 qv = *(const float4*)&q[(size_t)row * DM + t * 4];
    float4 xv = *(const float4*)&x[(size_t)row * DM + t * 4];
    float v0 = qv.x + xv.x, v1 = qv.y + xv.y, v2 = qv.z + xv.z, v3 = qv.w + xv.w;

    float s = v0 + v1 + v2 + v3;
#pragma unroll
    for (int o = 16; o > 0; o >>= 1) s += __shfl_xor_sync(0xffffffffu, s, o);
    if ((t & 31) == 0) red[t >> 5] = s;
    __syncthreads();
    if (t == 0) {
        float tot = 0.f;
#pragma unroll
        for (int i = 0; i < 8; i++) tot += red[i];
        s_mu = tot * (1.f / DM);
    }
    __syncthreads();
    float mu = s_mu;
    float d0 = v0 - mu, d1 = v1 - mu, d2 = v2 - mu, d3 = v3 - mu;
    float sq = d0 * d0 + d1 * d1 + d2 * d2 + d3 * d3;
#pragma unroll
    for (int o = 16; o > 0; o >>= 1) sq += __shfl_xor_sync(0xffffffffu, sq, o);
    if ((t & 31) == 0) red[t >> 5] = sq;
    __syncthreads();
    if (t == 0) {
        float tot = 0.f;
#pragma unroll
        for (int i = 0; i < 8; i++) tot += red[i];
        s_var = tot * (1.f / DM);
    }
    __syncthreads();
    float inv = rsqrtf(s_var + LN_EPS);
    float4 gv = *(const float4*)&gamma[t * 4];
    float4 bv = *(const float4*)&beta[t * 4];
    float4 w = make_float4(d0 * inv * gv.x + bv.x, d1 * inv * gv.y + bv.y,
                           d2 * inv * gv.z + bv.z, d3 * inv * gv.w + bv.w);
    *(float4*)&out[(size_t)row * DM + t * 4] = w;
}

// ---------------- launch ---------------------------------------------------
extern "C" void kernel_launch(void* const* d_in, const int* in_sizes, int n_in,
                              void* d_out, int out_size)
{
    const float* query   = (const float*)d_in[0];
    const float* content = (const float*)d_in[1];
    const float* r       = (const float*)d_in[2];
    const float* mems    = (const float*)d_in[3];
    // d_in[4] attn_mask: structural (j > i + MLEN), computed in-kernel
    const float* Wq    = (const float*)d_in[5];
    const float* Wk    = (const float*)d_in[6];
    const float* Wv    = (const float*)d_in[7];
    const float* Wr    = (const float*)d_in[8];
    const float* Wo    = (const float*)d_in[9];
    const float* rwb   = (const float*)d_in[10];
    const float* rrb   = (const float*)d_in[11];
    const float* gamma = (const float*)d_in[12];
    const float* beta  = (const float*)d_in[13];
    float* out = (float*)d_out;

    float *Qh, *Kh, *Vh, *Rh, *att, *ao;
    cudaGetSymbolAddress((void**)&Qh, g_Qh);
    cudaGetSymbolAddress((void**)&Kh, g_Kh);
    cudaGetSymbolAddress((void**)&Vh, g_Vh);
    cudaGetSymbolAddress((void**)&Rh, g_Rh);
    cudaGetSymbolAddress((void**)&att, g_att);
    cudaGetSymbolAddress((void**)&ao, g_ao);

    dim3 blk(256);
    // projections
    sgemm_cat<<<dim3(8, 32), blk>>>(query, query, QLEN * BSZ, Wq, Qh, QLEN * BSZ, DM, DM);
    sgemm_cat<<<dim3(8, 64), blk>>>(mems, content, MLEN * BSZ, Wk, Kh, KLEN * BSZ, DM, DM);
    sgemm_cat<<<dim3(8, 64), blk>>>(mems, content, MLEN * BSZ, Wv, Vh, KLEN * BSZ, DM, DM);
    sgemm_cat<<<dim3(8, 16), blk>>>(r, r, RLEN, Wr, Rh, RLEN, DM, DM);

    // fused rel-attention
    const int attn_smem = (5 * BI + 2 * BI) * SSTR * (int)sizeof(float);  // 448*68*4
    cudaFuncSetAttribute(attn_kernel, cudaFuncAttributeMaxDynamicSharedMemorySize, attn_smem);
    attn_kernel<<<dim3(QLEN / BI, BSZ, NH), blk, attn_smem>>>(rwb, rrb);

    // output projection + residual LN
    sgemm_cat<<<dim3(8, 32), blk>>>(att, att, QLEN * BSZ, Wo, ao, QLEN * BSZ, DM, DM);
    add_ln_kernel<<<QLEN * BSZ, 256>>>(query, ao, gamma, beta, out);
}